// round 15
// baseline (speedup 1.0000x reference)
#include <cuda_runtime.h>
#include <cuda_fp16.h>

#define NMAX 100000
#define EMAX 1600000
#define TMAX (NMAX + EMAX)

// ---------------- scratch (static device globals; no allocation) ----------------
__device__ int    g_deg[NMAX];
__device__ int    g_rowptr[NMAX + 1];
__device__ int    g_cursor[NMAX];
__device__ int    g_csrc[TMAX];

__device__ __half2 g_h1h[NMAX * 64];   // layer1 features (x@W1), 128ch as 64 half2
__device__ float4  g_as1[NMAX];        // h . a_src per node, 4 heads
__device__ float4  g_ad1[NMAX];        // h . a_dst per node, 4 heads
__device__ float4  g_alpha1[TMAX];     // unnormalized softmax weight per CSR entry, 4 heads
__device__ float4  g_r1[NMAX];         // 1/denominator per node, 4 heads

__device__ __half2 g_h1ah[NMAX * 64];  // relu(agg1 + b1): layer2 input, half2
__device__ __half2 g_h2h[NMAX * 16];   // layer2 pre-attention features, 32ch half2
__device__ float   g_as2[NMAX];
__device__ float   g_ad2[NMAX];
__device__ float   g_alpha2[TMAX];
__device__ float   g_r2[NMAX];
__device__ float   g_vs2[128];         // W2 @ a_src2
__device__ float   g_vd2[128];         // W2 @ a_dst2

__device__ __forceinline__ float lrelu(float x) { return x > 0.f ? x : 0.2f * x; }

__device__ __forceinline__ void mma16816(float* d, unsigned a0, unsigned a1,
                                         unsigned a2, unsigned a3,
                                         unsigned b0, unsigned b1) {
    asm volatile(
        "mma.sync.aligned.m16n8k16.row.col.f32.f16.f16.f32 "
        "{%0,%1,%2,%3}, {%4,%5,%6,%7}, {%8,%9}, {%0,%1,%2,%3};\n"
        : "+f"(d[0]), "+f"(d[1]), "+f"(d[2]), "+f"(d[3])
        : "r"(a0), "r"(a1), "r"(a2), "r"(a3), "r"(b0), "r"(b1));
}

// ---------------- v-vector precompute: v_s = W2 @ a_src2, v_d = W2 @ a_dst2 ----------------
__global__ void vker_kernel(const float* __restrict__ W2, const float* __restrict__ as2w,
                            const float* __restrict__ ad2w) {
    int k = threadIdx.x;  // 128 threads
    float s = 0.f, d = 0.f;
#pragma unroll 8
    for (int c = 0; c < 32; c++) {
        float w = W2[k * 32 + c];
        s += w * as2w[c];
        d += w * ad2w[c];
    }
    g_vs2[k] = s;
    g_vd2[k] = d;
}

// ---------------- CSR build ----------------
__global__ void hist_kernel(const int* __restrict__ ei, int E) {
    int e = blockIdx.x * blockDim.x + threadIdx.x;
    if (e < E) atomicAdd(&g_deg[ei[E + e]], 1);
}

// deg[] holds in-edge counts (memset 0 beforehand); +1 per node for the self loop.
__global__ void scan_kernel(int N) {
    __shared__ int s[1024];
    int t = threadIdx.x;
    int chunk = (N + 1023) >> 10;
    int lo = t * chunk;
    int hi = min(lo + chunk, N);
    int sum = 0;
    for (int i = lo; i < hi; i++) sum += g_deg[i] + 1;
    s[t] = sum;
    __syncthreads();
    for (int off = 1; off < 1024; off <<= 1) {
        int v = (t >= off) ? s[t - off] : 0;
        __syncthreads();
        s[t] += v;
        __syncthreads();
    }
    int run = (t > 0) ? s[t - 1] : 0;
    for (int i = lo; i < hi; i++) { g_rowptr[i] = run; run += g_deg[i] + 1; }
    if (t == 1023) g_rowptr[N] = s[1023];
}

__global__ void fillself_kernel(int N) {
    int n = blockIdx.x * blockDim.x + threadIdx.x;
    if (n < N) {
        int r = g_rowptr[n];
        g_csrc[r] = n;         // self loop first
        g_cursor[n] = r + 1;
    }
}

__global__ void filledge_kernel(const int* __restrict__ ei, int E) {
    int e = blockIdx.x * blockDim.x + threadIdx.x;
    if (e < E) {
        int dst = ei[E + e];
        int pos = atomicAdd(&g_cursor[dst], 1);
        g_csrc[pos] = ei[e];
    }
}

// ---------------- GEMM1 (tensor): h1[N,128] = X[N,64] @ W1[64,128] + coef epilogue ----
__global__ void __launch_bounds__(256) gemm1_kernel(
    const float* __restrict__ X, const float* __restrict__ W,
    const float* __restrict__ a_src, const float* __restrict__ a_dst, int N) {
    __shared__ __half xs[64 * 72];    // [node][k], stride 72
    __shared__ __half ws[128 * 72];   // W transposed: [n][k], stride 72

    int t = threadIdx.x;
    int lane = t & 31;
    int w = t >> 5;
    int gid = lane >> 2;
    int tig = lane & 3;
    int n0 = blockIdx.x * 64;

#pragma unroll
    for (int r = 0; r < 4; r++) {
        int f = t + r * 256;
        int node = f >> 4;
        int kk = (f & 15) << 2;
        int gn = n0 + node;
        float4 v = make_float4(0.f, 0.f, 0.f, 0.f);
        if (gn < N) v = *(const float4*)&X[(size_t)gn * 64 + kk];
        __half2* dst = (__half2*)&xs[node * 72 + kk];
        dst[0] = __floats2half2_rn(v.x, v.y);
        dst[1] = __floats2half2_rn(v.z, v.w);
    }
#pragma unroll
    for (int r = 0; r < 32; r++) {
        int f = t + r * 256;            // k*128 + n
        int k = f >> 7;
        int n = f & 127;
        ws[n * 72 + k] = __float2half(W[f]);
    }
    __syncthreads();

    int m0 = (w & 3) * 16;
    int nbase = (w >> 2) * 64;
    float acc[8][4];
#pragma unroll
    for (int nf = 0; nf < 8; nf++)
#pragma unroll
        for (int i = 0; i < 4; i++) acc[nf][i] = 0.f;

#pragma unroll
    for (int ks = 0; ks < 4; ks++) {
        int k0 = ks * 16 + 2 * tig;
        unsigned a0 = *(const unsigned*)&xs[(m0 + gid) * 72 + k0];
        unsigned a1 = *(const unsigned*)&xs[(m0 + gid + 8) * 72 + k0];
        unsigned a2 = *(const unsigned*)&xs[(m0 + gid) * 72 + k0 + 8];
        unsigned a3 = *(const unsigned*)&xs[(m0 + gid + 8) * 72 + k0 + 8];
#pragma unroll
        for (int nf = 0; nf < 8; nf++) {
            int nn = nbase + nf * 8 + gid;
            unsigned b0 = *(const unsigned*)&ws[nn * 72 + k0];
            unsigned b1 = *(const unsigned*)&ws[nn * 72 + k0 + 8];
            mma16816(acc[nf], a0, a1, a2, a3, b0, b1);
        }
    }

    int gn0 = n0 + m0 + gid;
    int gn1 = gn0 + 8;
    float psA0 = 0.f, psA1 = 0.f, pdA0 = 0.f, pdA1 = 0.f;
    float psB0 = 0.f, psB1 = 0.f, pdB0 = 0.f, pdB1 = 0.f;
#pragma unroll
    for (int nf = 0; nf < 8; nf++) {
        int c = nbase + nf * 8 + 2 * tig;
        float avx = a_src[c], avy = a_src[c + 1];
        float dvx = a_dst[c], dvy = a_dst[c + 1];
        float p0s = acc[nf][0] * avx + acc[nf][1] * avy;
        float p1s = acc[nf][2] * avx + acc[nf][3] * avy;
        float p0d = acc[nf][0] * dvx + acc[nf][1] * dvy;
        float p1d = acc[nf][2] * dvx + acc[nf][3] * dvy;
        if (nf < 4) { psA0 += p0s; psA1 += p1s; pdA0 += p0d; pdA1 += p1d; }
        else        { psB0 += p0s; psB1 += p1s; pdB0 += p0d; pdB1 += p1d; }
        if (gn0 < N) g_h1h[(size_t)gn0 * 64 + (c >> 1)] = __floats2half2_rn(acc[nf][0], acc[nf][1]);
        if (gn1 < N) g_h1h[(size_t)gn1 * 64 + (c >> 1)] = __floats2half2_rn(acc[nf][2], acc[nf][3]);
    }
#pragma unroll
    for (int off = 1; off <= 2; off <<= 1) {
        psA0 += __shfl_xor_sync(0xffffffffu, psA0, off);
        psA1 += __shfl_xor_sync(0xffffffffu, psA1, off);
        pdA0 += __shfl_xor_sync(0xffffffffu, pdA0, off);
        pdA1 += __shfl_xor_sync(0xffffffffu, pdA1, off);
        psB0 += __shfl_xor_sync(0xffffffffu, psB0, off);
        psB1 += __shfl_xor_sync(0xffffffffu, psB1, off);
        pdB0 += __shfl_xor_sync(0xffffffffu, pdB0, off);
        pdB1 += __shfl_xor_sync(0xffffffffu, pdB1, off);
    }
    if (tig == 0) {
        float* asf = (float*)g_as1;
        float* adf = (float*)g_ad1;
        int hA = nbase >> 5;       // 0 or 2
        if (gn0 < N) {
            asf[gn0 * 4 + hA] = psA0;  asf[gn0 * 4 + hA + 1] = psB0;
            adf[gn0 * 4 + hA] = pdA0;  adf[gn0 * 4 + hA + 1] = pdB0;
        }
        if (gn1 < N) {
            asf[gn1 * 4 + hA] = psA1;  asf[gn1 * 4 + hA + 1] = psB1;
            adf[gn1 * 4 + hA] = pdA1;  adf[gn1 * 4 + hA + 1] = pdB1;
        }
    }
}

// ---------------- layer 1: per-edge unnormalized alpha + per-node denominators ----------------
__global__ void alpha1_kernel(int N) {
    int n = (blockIdx.x * blockDim.x + threadIdx.x) >> 5;
    int lane = threadIdx.x & 31;
    if (n >= N) return;
    float4 ad = g_ad1[n];
    int beg = g_rowptr[n], end = g_rowptr[n + 1];
    float4 ds = make_float4(0.f, 0.f, 0.f, 0.f);
    for (int i = beg + lane; i < end; i += 32) {
        int s = g_csrc[i];
        float4 as = g_as1[s];
        float4 w;
        w.x = __expf(lrelu(as.x + ad.x));
        w.y = __expf(lrelu(as.y + ad.y));
        w.z = __expf(lrelu(as.z + ad.z));
        w.w = __expf(lrelu(as.w + ad.w));
        g_alpha1[i] = w;
        ds.x += w.x; ds.y += w.y; ds.z += w.z; ds.w += w.w;
    }
#pragma unroll
    for (int off = 16; off > 0; off >>= 1) {
        ds.x += __shfl_xor_sync(0xffffffffu, ds.x, off);
        ds.y += __shfl_xor_sync(0xffffffffu, ds.y, off);
        ds.z += __shfl_xor_sync(0xffffffffu, ds.z, off);
        ds.w += __shfl_xor_sync(0xffffffffu, ds.w, off);
    }
    if (lane == 0)
        g_r1[n] = make_float4(1.f / ds.x, 1.f / ds.y, 1.f / ds.z, 1.f / ds.w);
}

// ---------------- layer 1: aggregation + bias + relu + layer2-coef epilogue ----------------
// warp per node; half-warp per edge, lane owns 8 channels via one int4 load.
// Epilogue also computes as2[n] = h1a[n].v_s, ad2[n] = h1a[n].v_d (quantized-half h1a).
__global__ void agg1_kernel(const float* __restrict__ b1, int N) {
    int n = (blockIdx.x * blockDim.x + threadIdx.x) >> 5;
    int lane = threadIdx.x & 31;
    if (n >= N) return;
    int half = lane >> 4;
    int c = lane & 15;
    int h = c >> 2;
    const float* af = (const float*)g_alpha1;
    const int4* h1p = (const int4*)g_h1h;   // row = 16 int4

    int beg = g_rowptr[n], end = g_rowptr[n + 1];
    float a0 = 0.f, a1 = 0.f, a2 = 0.f, a3 = 0.f;
    float a4 = 0.f, a5 = 0.f, a6 = 0.f, a7 = 0.f;

#define AGG1_ACC(P, W)                                                          \
    {                                                                           \
        float2 f;                                                               \
        f = __half22float2(*(__half2*)&(P).x); a0 += (W) * f.x; a1 += (W) * f.y;\
        f = __half22float2(*(__half2*)&(P).y); a2 += (W) * f.x; a3 += (W) * f.y;\
        f = __half22float2(*(__half2*)&(P).z); a4 += (W) * f.x; a5 += (W) * f.y;\
        f = __half22float2(*(__half2*)&(P).w); a6 += (W) * f.x; a7 += (W) * f.y;\
    }

    int i = beg;
    for (; i + 4 <= end; i += 4) {
        int ii0 = i + half;
        int ii1 = i + 2 + half;
        int s0 = g_csrc[ii0];
        int s1 = g_csrc[ii1];
        float w0 = af[(size_t)ii0 * 4 + h];
        float w1 = af[(size_t)ii1 * 4 + h];
        int4 p0 = h1p[(size_t)s0 * 16 + c];
        int4 p1 = h1p[(size_t)s1 * 16 + c];
        AGG1_ACC(p0, w0)
        AGG1_ACC(p1, w1)
    }
    for (; i < end; i += 2) {
        int ii = i + half;
        if (ii < end) {
            int s = g_csrc[ii];
            float w0 = af[(size_t)ii * 4 + h];
            int4 p = h1p[(size_t)s * 16 + c];
            AGG1_ACC(p, w0)
        }
    }
#undef AGG1_ACC

    // combine halves: lanes c and c+16 hold partials of the same channels
    a0 += __shfl_xor_sync(0xffffffffu, a0, 16);
    a1 += __shfl_xor_sync(0xffffffffu, a1, 16);
    a2 += __shfl_xor_sync(0xffffffffu, a2, 16);
    a3 += __shfl_xor_sync(0xffffffffu, a3, 16);
    a4 += __shfl_xor_sync(0xffffffffu, a4, 16);
    a5 += __shfl_xor_sync(0xffffffffu, a5, 16);
    a6 += __shfl_xor_sync(0xffffffffu, a6, 16);
    a7 += __shfl_xor_sync(0xffffffffu, a7, 16);

    // all lanes now hold the full sums for channels 8c..8c+7 (duplicated across halves)
    float r = ((const float*)g_r1)[(size_t)n * 4 + h];
    float4 bv0 = ((const float4*)b1)[2 * c];
    float4 bv1 = ((const float4*)b1)[2 * c + 1];
    float o0 = fmaxf(a0 * r + bv0.x, 0.f);
    float o1 = fmaxf(a1 * r + bv0.y, 0.f);
    float o2 = fmaxf(a2 * r + bv0.z, 0.f);
    float o3 = fmaxf(a3 * r + bv0.w, 0.f);
    float o4 = fmaxf(a4 * r + bv1.x, 0.f);
    float o5 = fmaxf(a5 * r + bv1.y, 0.f);
    float o6 = fmaxf(a6 * r + bv1.z, 0.f);
    float o7 = fmaxf(a7 * r + bv1.w, 0.f);
    int4 st;
    *(__half2*)&st.x = __floats2half2_rn(o0, o1);
    *(__half2*)&st.y = __floats2half2_rn(o2, o3);
    *(__half2*)&st.z = __floats2half2_rn(o4, o5);
    *(__half2*)&st.w = __floats2half2_rn(o6, o7);
    if (half == 0) {
        ((int4*)g_h1ah)[(size_t)n * 16 + c] = st;
    }

    // layer-2 coefficients: dot the quantized (half-rounded) h1a with v_s, v_d.
    float2 q01 = __half22float2(*(__half2*)&st.x);
    float2 q23 = __half22float2(*(__half2*)&st.y);
    float2 q45 = __half22float2(*(__half2*)&st.z);
    float2 q67 = __half22float2(*(__half2*)&st.w);
    float4 vs0 = ((const float4*)g_vs2)[2 * c];
    float4 vs1 = ((const float4*)g_vs2)[2 * c + 1];
    float4 vd0 = ((const float4*)g_vd2)[2 * c];
    float4 vd1 = ((const float4*)g_vd2)[2 * c + 1];
    float ps = q01.x * vs0.x + q01.y * vs0.y + q23.x * vs0.z + q23.y * vs0.w
             + q45.x * vs1.x + q45.y * vs1.y + q67.x * vs1.z + q67.y * vs1.w;
    float pd = q01.x * vd0.x + q01.y * vd0.y + q23.x * vd0.z + q23.y * vd0.w
             + q45.x * vd1.x + q45.y * vd1.y + q67.x * vd1.z + q67.y * vd1.w;
#pragma unroll
    for (int off = 1; off <= 16; off <<= 1) {
        ps += __shfl_xor_sync(0xffffffffu, ps, off);
        pd += __shfl_xor_sync(0xffffffffu, pd, off);
    }
    if (lane == 0) {
        g_as2[n] = ps * 0.5f;   // halves duplicated -> sum counted twice
        g_ad2[n] = pd * 0.5f;
    }
}

// ---------------- GEMM2 (tensor): h2[N,32] = h1a[N,128](f16) @ W2[128,32] ----------------
__global__ void __launch_bounds__(128) gemm2_kernel(const float* __restrict__ W, int N) {
    __shared__ __half xs[64 * 136];   // [node][k], stride 136
    __shared__ __half ws[32 * 136];   // W transposed: [n][k], stride 136

    int t = threadIdx.x;
    int lane = t & 31;
    int w = t >> 5;
    int gid = lane >> 2;
    int tig = lane & 3;
    int n0 = blockIdx.x * 64;

#pragma unroll
    for (int r = 0; r < 8; r++) {
        int f = t + r * 128;
        int node = f >> 4;
        int part = f & 15;
        int gn = n0 + node;
        int4 v = make_int4(0, 0, 0, 0);
        if (gn < N) v = ((const int4*)g_h1ah)[(size_t)gn * 16 + part];
        ((int4*)xs)[node * 17 + part] = v;
    }
#pragma unroll
    for (int r = 0; r < 32; r++) {
        int f = t + r * 128;            // k*32 + n
        int k = f >> 5;
        int n = f & 31;
        ws[n * 136 + k] = __float2half(W[f]);
    }
    __syncthreads();

    int m0 = w * 16;
    float acc[4][4];
#pragma unroll
    for (int nf = 0; nf < 4; nf++)
#pragma unroll
        for (int i = 0; i < 4; i++) acc[nf][i] = 0.f;

#pragma unroll
    for (int ks = 0; ks < 8; ks++) {
        int k0 = ks * 16 + 2 * tig;
        unsigned a0 = *(const unsigned*)&xs[(m0 + gid) * 136 + k0];
        unsigned a1 = *(const unsigned*)&xs[(m0 + gid + 8) * 136 + k0];
        unsigned a2 = *(const unsigned*)&xs[(m0 + gid) * 136 + k0 + 8];
        unsigned a3 = *(const unsigned*)&xs[(m0 + gid + 8) * 136 + k0 + 8];
#pragma unroll
        for (int nf = 0; nf < 4; nf++) {
            int nn = nf * 8 + gid;
            unsigned b0 = *(const unsigned*)&ws[nn * 136 + k0];
            unsigned b1 = *(const unsigned*)&ws[nn * 136 + k0 + 8];
            mma16816(acc[nf], a0, a1, a2, a3, b0, b1);
        }
    }

    int gn0 = n0 + m0 + gid;
    int gn1 = gn0 + 8;
#pragma unroll
    for (int nf = 0; nf < 4; nf++) {
        int c = nf * 8 + 2 * tig;
        if (gn0 < N) g_h2h[(size_t)gn0 * 16 + (c >> 1)] = __floats2half2_rn(acc[nf][0], acc[nf][1]);
        if (gn1 < N) g_h2h[(size_t)gn1 * 16 + (c >> 1)] = __floats2half2_rn(acc[nf][2], acc[nf][3]);
    }
}

// ---------------- layer 2: per-edge alpha + denominators ----------------
__global__ void alpha2_kernel(int N) {
    int n = (blockIdx.x * blockDim.x + threadIdx.x) >> 5;
    int lane = threadIdx.x & 31;
    if (n >= N) return;
    float ad = g_ad2[n];
    int beg = g_rowptr[n], end = g_rowptr[n + 1];
    float ds = 0.f;
    for (int i = beg + lane; i < end; i += 32) {
        float w = __expf(lrelu(g_as2[g_csrc[i]] + ad));
        g_alpha2[i] = w;
        ds += w;
    }
#pragma unroll
    for (int off = 16; off > 0; off >>= 1) ds += __shfl_xor_sync(0xffffffffu, ds, off);
    if (lane == 0) g_r2[n] = 1.f / ds;
}

// ---------------- layer 2: aggregation + bias + relu + final linear ----------------
// warp per node; quarter-warp per edge (4 edges/iter), lane owns channels {4c..4c+3}.
__global__ void agg2_kernel(const float* __restrict__ b2, const float* __restrict__ Wl,
                            const float* __restrict__ bl, float* __restrict__ out, int N) {
    int n = (blockIdx.x * blockDim.x + threadIdx.x) >> 5;
    int lane = threadIdx.x & 31;
    if (n >= N) return;
    int q = lane >> 3;
    int c = lane & 7;
    const int2* h2p = (const int2*)g_h2h;   // row = 8 int2
    int beg = g_rowptr[n], end = g_rowptr[n + 1];

    float4 acc = make_float4(0.f, 0.f, 0.f, 0.f);

#define AGG2_ACC(P, W)                                                          \
    {                                                                           \
        float2 f;                                                               \
        f = __half22float2(*(__half2*)&(P).x); acc.x += (W) * f.x; acc.y += (W) * f.y; \
        f = __half22float2(*(__half2*)&(P).y); acc.z += (W) * f.x; acc.w += (W) * f.y; \
    }

    int i = beg;
    for (; i + 8 <= end; i += 8) {
        int ii0 = i + q;
        int ii1 = i + 4 + q;
        int s0 = g_csrc[ii0];
        int s1 = g_csrc[ii1];
        float w0 = g_alpha2[ii0];
        float w1 = g_alpha2[ii1];
        int2 p0 = h2p[(size_t)s0 * 8 + c];
        int2 p1 = h2p[(size_t)s1 * 8 + c];
        AGG2_ACC(p0, w0)
        AGG2_ACC(p1, w1)
    }
    for (; i < end; i += 4) {
        int ii = i + q;
        if (ii < end) {
            int s = g_csrc[ii];
            float w = g_alpha2[ii];
            int2 p = h2p[(size_t)s * 8 + c];
            AGG2_ACC(p, w)
        }
    }
#undef AGG2_ACC

    // combine quarters: all lanes with the same c end up with the full channel sums
    acc.x += __shfl_xor_sync(0xffffffffu, acc.x, 8);
    acc.y += __shfl_xor_sync(0xffffffffu, acc.y, 8);
    acc.z += __shfl_xor_sync(0xffffffffu, acc.z, 8);
    acc.w += __shfl_xor_sync(0xffffffffu, acc.w, 8);
    acc.x += __shfl_xor_sync(0xffffffffu, acc.x, 16);
    acc.y += __shfl_xor_sync(0xffffffffu, acc.y, 16);
    acc.z += __shfl_xor_sync(0xffffffffu, acc.z, 16);
    acc.w += __shfl_xor_sync(0xffffffffu, acc.w, 16);

    float r = g_r2[n];
    float4 bv = ((const float4*)b2)[c];
    float4 wl = ((const float4*)Wl)[c];
    float v = fmaxf(acc.x * r + bv.x, 0.f) * wl.x
            + fmaxf(acc.y * r + bv.y, 0.f) * wl.y
            + fmaxf(acc.z * r + bv.z, 0.f) * wl.z
            + fmaxf(acc.w * r + bv.w, 0.f) * wl.w;
#pragma unroll
    for (int off = 1; off <= 4; off <<= 1) v += __shfl_xor_sync(0xffffffffu, v, off);
    if (lane == 0) out[n] = v + bl[0];
}

// ---------------- launch ----------------
extern "C" void kernel_launch(void* const* d_in, const int* in_sizes, int n_in,
                              void* d_out, int out_size) {
    const float* x    = (const float*)d_in[0];
    const int*   ei   = (const int*)d_in[1];
    const float* W1   = (const float*)d_in[3];
    const float* as1w = (const float*)d_in[4];
    const float* ad1w = (const float*)d_in[5];
    const float* b1   = (const float*)d_in[6];
    const float* W2   = (const float*)d_in[7];
    const float* as2w = (const float*)d_in[8];
    const float* ad2w = (const float*)d_in[9];
    const float* b2   = (const float*)d_in[10];
    const float* Wl   = (const float*)d_in[11];
    const float* bl   = (const float*)d_in[12];
    float* out = (float*)d_out;

    int N = in_sizes[0] / 64;
    int E = in_sizes[1] / 2;

    static cudaStream_t s2 = nullptr;
    static cudaEvent_t evRoot = nullptr, evGemm = nullptr, evAgg = nullptr, evGemm2 = nullptr;
    static int* degPtr = nullptr;
    if (s2 == nullptr) {  // one-time resource setup (first call is the uncaptured correctness run)
        cudaStreamCreateWithFlags(&s2, cudaStreamNonBlocking);
        cudaEventCreateWithFlags(&evRoot, cudaEventDisableTiming);
        cudaEventCreateWithFlags(&evGemm, cudaEventDisableTiming);
        cudaEventCreateWithFlags(&evAgg, cudaEventDisableTiming);
        cudaEventCreateWithFlags(&evGemm2, cudaEventDisableTiming);
        cudaGetSymbolAddress((void**)&degPtr, g_deg);
    }

    int nb = (N + 255) / 256;
    int eb = (E + 255) / 256;
    int wb = (N + 7) / 8;  // warp-per-node, 8 warps per 256-thread block

    // fork: v-vectors + gemm1 (independent of the graph) run on s2, overlapped with CSR build
    cudaEventRecord(evRoot, 0);
    cudaStreamWaitEvent(s2, evRoot, 0);
    vker_kernel<<<1, 128, 0, s2>>>(W2, as2w, ad2w);
    gemm1_kernel<<<(N + 63) / 64, 256, 0, s2>>>(x, W1, as1w, ad1w, N);
    cudaEventRecord(evGemm, s2);

    // CSR build on the main stream
    cudaMemsetAsync(degPtr, 0, (size_t)N * sizeof(int), 0);
    hist_kernel<<<eb, 256>>>(ei, E);
    scan_kernel<<<1, 1024>>>(N);
    fillself_kernel<<<nb, 256>>>(N);
    filledge_kernel<<<eb, 256>>>(ei, E);

    // join: alpha1 needs both gemm1 outputs and the CSR
    cudaStreamWaitEvent(0, evGemm, 0);

    // layer 1 (agg1 also produces layer-2 coefficients as2/ad2)
    alpha1_kernel<<<wb, 256>>>(N);
    agg1_kernel<<<wb, 256>>>(b1, N);
    cudaEventRecord(evAgg, 0);

    // fork: gemm2 (h2 only) on s2 concurrent with alpha2 on main
    cudaStreamWaitEvent(s2, evAgg, 0);
    gemm2_kernel<<<(N + 63) / 64, 128, 0, s2>>>(W2, N);
    cudaEventRecord(evGemm2, s2);

    alpha2_kernel<<<wb, 256>>>(N);

    // join: agg2 needs h2 (s2) and alpha2 (main)
    cudaStreamWaitEvent(0, evGemm2, 0);
    agg2_kernel<<<wb, 256>>>(b2, Wl, bl, out, N);
}

// round 16
// speedup vs baseline: 1.5861x; 1.5861x over previous
#include <cuda_runtime.h>
#include <cuda_fp16.h>

#define NMAX 100000
#define EMAX 1600000
#define TMAX (NMAX + EMAX)

#define SBLK 256
#define SPER 16
#define SNODES (SBLK * SPER)   // 4096 nodes per scan block
#define SGRID ((NMAX + SNODES - 1) / SNODES)   // 25

// ---------------- scratch (static device globals; no allocation) ----------------
__device__ int    g_deg[NMAX];
__device__ int    g_rowptr[NMAX + 1];
__device__ int    g_cursor[NMAX];
__device__ int    g_csrc[TMAX];
__device__ int    g_bsum[64];
__device__ int    g_boff[64];

__device__ __half2 g_h1h[NMAX * 64];   // layer1 features (x@W1), 128ch as 64 half2
__device__ float4  g_as1[NMAX];        // h . a_src per node, 4 heads
__device__ float4  g_ad1[NMAX];        // h . a_dst per node, 4 heads
__device__ float4  g_alpha1[TMAX];     // unnormalized softmax weight per CSR entry, 4 heads
__device__ float4  g_r1[NMAX];         // 1/denominator per node, 4 heads

__device__ __half2 g_h1ah[NMAX * 64];  // relu(agg1 + b1): layer2 input, half2
__device__ __half2 g_h2h[NMAX * 16];   // layer2 pre-attention features, 32ch half2
__device__ float   g_as2[NMAX];
__device__ float   g_ad2[NMAX];
__device__ float   g_alpha2[TMAX];
__device__ float   g_r2[NMAX];

__device__ __forceinline__ float lrelu(float x) { return x > 0.f ? x : 0.2f * x; }

__device__ __forceinline__ void mma16816(float* d, unsigned a0, unsigned a1,
                                         unsigned a2, unsigned a3,
                                         unsigned b0, unsigned b1) {
    asm volatile(
        "mma.sync.aligned.m16n8k16.row.col.f32.f16.f16.f32 "
        "{%0,%1,%2,%3}, {%4,%5,%6,%7}, {%8,%9}, {%0,%1,%2,%3};\n"
        : "+f"(d[0]), "+f"(d[1]), "+f"(d[2]), "+f"(d[3])
        : "r"(a0), "r"(a1), "r"(a2), "r"(a3), "r"(b0), "r"(b1));
}

// ---------------- CSR build ----------------
__global__ void hist_kernel(const int* __restrict__ ei, int E) {
    int e = blockIdx.x * blockDim.x + threadIdx.x;
    if (e < E) atomicAdd(&g_deg[ei[E + e]], 1);
}

// phase A: per-block sums of (deg+1)
__global__ void scanA_kernel(int N) {
    __shared__ int s[SBLK];
    int t = threadIdx.x;
    int lo = blockIdx.x * SNODES + t * SPER;
    int hi = min(lo + SPER, N);
    int sum = 0;
    for (int i = lo; i < hi; i++) sum += g_deg[i] + 1;
    s[t] = sum;
    __syncthreads();
    for (int off = SBLK / 2; off > 0; off >>= 1) {
        if (t < off) s[t] += s[t + off];
        __syncthreads();
    }
    if (t == 0) g_bsum[blockIdx.x] = s[0];
}

// phase B: exclusive scan of block sums (<=64), writes rowptr[N]
__global__ void scanB_kernel(int nb, int N) {
    __shared__ int s[64];
    int t = threadIdx.x;  // 64 threads
    int v = (t < nb) ? g_bsum[t] : 0;
    s[t] = v;
    __syncthreads();
    for (int off = 1; off < 64; off <<= 1) {
        int u = (t >= off) ? s[t - off] : 0;
        __syncthreads();
        s[t] += u;
        __syncthreads();
    }
    if (t < nb) g_boff[t] = s[t] - v;   // exclusive block offset
    if (t == nb - 1) g_rowptr[N] = s[t];
}

// phase C: full scan within block + rowptr/self-loop/cursor emission
__global__ void scanC_kernel(int N) {
    __shared__ int s[SBLK];
    int t = threadIdx.x;
    int lo = blockIdx.x * SNODES + t * SPER;
    int hi = min(lo + SPER, N);
    int sum = 0;
    for (int i = lo; i < hi; i++) sum += g_deg[i] + 1;
    s[t] = sum;
    __syncthreads();
    for (int off = 1; off < SBLK; off <<= 1) {
        int u = (t >= off) ? s[t - off] : 0;
        __syncthreads();
        s[t] += u;
        __syncthreads();
    }
    int run = g_boff[blockIdx.x] + s[t] - sum;  // exclusive prefix for this thread's chunk
    for (int i = lo; i < hi; i++) {
        g_rowptr[i] = run;
        g_csrc[run] = i;       // self loop first
        g_cursor[i] = run + 1;
        run += g_deg[i] + 1;
    }
}

__global__ void filledge_kernel(const int* __restrict__ ei, int E) {
    int e = blockIdx.x * blockDim.x + threadIdx.x;
    if (e < E) {
        int dst = ei[E + e];
        int pos = atomicAdd(&g_cursor[dst], 1);
        g_csrc[pos] = ei[e];
    }
}

// ---------------- GEMM1 (tensor): h1[N,128] = X[N,64] @ W1[64,128] + coef epilogue ----
__global__ void __launch_bounds__(256) gemm1_kernel(
    const float* __restrict__ X, const float* __restrict__ W,
    const float* __restrict__ a_src, const float* __restrict__ a_dst, int N) {
    __shared__ __half xs[64 * 72];    // [node][k], stride 72
    __shared__ __half ws[128 * 72];   // W transposed: [n][k], stride 72

    int t = threadIdx.x;
    int lane = t & 31;
    int w = t >> 5;
    int gid = lane >> 2;
    int tig = lane & 3;
    int n0 = blockIdx.x * 64;

#pragma unroll
    for (int r = 0; r < 4; r++) {
        int f = t + r * 256;
        int node = f >> 4;
        int kk = (f & 15) << 2;
        int gn = n0 + node;
        float4 v = make_float4(0.f, 0.f, 0.f, 0.f);
        if (gn < N) v = *(const float4*)&X[(size_t)gn * 64 + kk];
        __half2* dst = (__half2*)&xs[node * 72 + kk];
        dst[0] = __floats2half2_rn(v.x, v.y);
        dst[1] = __floats2half2_rn(v.z, v.w);
    }
#pragma unroll
    for (int r = 0; r < 32; r++) {
        int f = t + r * 256;            // k*128 + n
        int k = f >> 7;
        int n = f & 127;
        ws[n * 72 + k] = __float2half(W[f]);
    }
    __syncthreads();

    int m0 = (w & 3) * 16;
    int nbase = (w >> 2) * 64;
    float acc[8][4];
#pragma unroll
    for (int nf = 0; nf < 8; nf++)
#pragma unroll
        for (int i = 0; i < 4; i++) acc[nf][i] = 0.f;

#pragma unroll
    for (int ks = 0; ks < 4; ks++) {
        int k0 = ks * 16 + 2 * tig;
        unsigned a0 = *(const unsigned*)&xs[(m0 + gid) * 72 + k0];
        unsigned a1 = *(const unsigned*)&xs[(m0 + gid + 8) * 72 + k0];
        unsigned a2 = *(const unsigned*)&xs[(m0 + gid) * 72 + k0 + 8];
        unsigned a3 = *(const unsigned*)&xs[(m0 + gid + 8) * 72 + k0 + 8];
#pragma unroll
        for (int nf = 0; nf < 8; nf++) {
            int nn = nbase + nf * 8 + gid;
            unsigned b0 = *(const unsigned*)&ws[nn * 72 + k0];
            unsigned b1 = *(const unsigned*)&ws[nn * 72 + k0 + 8];
            mma16816(acc[nf], a0, a1, a2, a3, b0, b1);
        }
    }

    int gn0 = n0 + m0 + gid;
    int gn1 = gn0 + 8;
    float psA0 = 0.f, psA1 = 0.f, pdA0 = 0.f, pdA1 = 0.f;
    float psB0 = 0.f, psB1 = 0.f, pdB0 = 0.f, pdB1 = 0.f;
#pragma unroll
    for (int nf = 0; nf < 8; nf++) {
        int c = nbase + nf * 8 + 2 * tig;
        float avx = a_src[c], avy = a_src[c + 1];
        float dvx = a_dst[c], dvy = a_dst[c + 1];
        float p0s = acc[nf][0] * avx + acc[nf][1] * avy;
        float p1s = acc[nf][2] * avx + acc[nf][3] * avy;
        float p0d = acc[nf][0] * dvx + acc[nf][1] * dvy;
        float p1d = acc[nf][2] * dvx + acc[nf][3] * dvy;
        if (nf < 4) { psA0 += p0s; psA1 += p1s; pdA0 += p0d; pdA1 += p1d; }
        else        { psB0 += p0s; psB1 += p1s; pdB0 += p0d; pdB1 += p1d; }
        if (gn0 < N) g_h1h[(size_t)gn0 * 64 + (c >> 1)] = __floats2half2_rn(acc[nf][0], acc[nf][1]);
        if (gn1 < N) g_h1h[(size_t)gn1 * 64 + (c >> 1)] = __floats2half2_rn(acc[nf][2], acc[nf][3]);
    }
#pragma unroll
    for (int off = 1; off <= 2; off <<= 1) {
        psA0 += __shfl_xor_sync(0xffffffffu, psA0, off);
        psA1 += __shfl_xor_sync(0xffffffffu, psA1, off);
        pdA0 += __shfl_xor_sync(0xffffffffu, pdA0, off);
        pdA1 += __shfl_xor_sync(0xffffffffu, pdA1, off);
        psB0 += __shfl_xor_sync(0xffffffffu, psB0, off);
        psB1 += __shfl_xor_sync(0xffffffffu, psB1, off);
        pdB0 += __shfl_xor_sync(0xffffffffu, pdB0, off);
        pdB1 += __shfl_xor_sync(0xffffffffu, pdB1, off);
    }
    if (tig == 0) {
        float* asf = (float*)g_as1;
        float* adf = (float*)g_ad1;
        int hA = nbase >> 5;       // 0 or 2
        if (gn0 < N) {
            asf[gn0 * 4 + hA] = psA0;  asf[gn0 * 4 + hA + 1] = psB0;
            adf[gn0 * 4 + hA] = pdA0;  adf[gn0 * 4 + hA + 1] = pdB0;
        }
        if (gn1 < N) {
            asf[gn1 * 4 + hA] = psA1;  asf[gn1 * 4 + hA + 1] = psB1;
            adf[gn1 * 4 + hA] = pdA1;  adf[gn1 * 4 + hA + 1] = pdB1;
        }
    }
}

// ---------------- layer 1: per-edge unnormalized alpha + per-node denominators ----------------
__global__ void alpha1_kernel(int N) {
    int n = (blockIdx.x * blockDim.x + threadIdx.x) >> 5;
    int lane = threadIdx.x & 31;
    if (n >= N) return;
    float4 ad = g_ad1[n];
    int beg = g_rowptr[n], end = g_rowptr[n + 1];
    float4 ds = make_float4(0.f, 0.f, 0.f, 0.f);
    for (int i = beg + lane; i < end; i += 32) {
        int s = g_csrc[i];
        float4 as = g_as1[s];
        float4 w;
        w.x = __expf(lrelu(as.x + ad.x));
        w.y = __expf(lrelu(as.y + ad.y));
        w.z = __expf(lrelu(as.z + ad.z));
        w.w = __expf(lrelu(as.w + ad.w));
        g_alpha1[i] = w;
        ds.x += w.x; ds.y += w.y; ds.z += w.z; ds.w += w.w;
    }
#pragma unroll
    for (int off = 16; off > 0; off >>= 1) {
        ds.x += __shfl_xor_sync(0xffffffffu, ds.x, off);
        ds.y += __shfl_xor_sync(0xffffffffu, ds.y, off);
        ds.z += __shfl_xor_sync(0xffffffffu, ds.z, off);
        ds.w += __shfl_xor_sync(0xffffffffu, ds.w, off);
    }
    if (lane == 0)
        g_r1[n] = make_float4(1.f / ds.x, 1.f / ds.y, 1.f / ds.z, 1.f / ds.w);
}

// ---------------- layer 1: aggregation + bias + relu (alpha precomputed) ----------------
// warp per node; half-warp per edge, lane owns 8 channels via one int4 load.
__global__ void agg1_kernel(const float* __restrict__ b1, int N) {
    int n = (blockIdx.x * blockDim.x + threadIdx.x) >> 5;
    int lane = threadIdx.x & 31;
    if (n >= N) return;
    int half = lane >> 4;
    int c = lane & 15;
    int h = c >> 2;
    const float* af = (const float*)g_alpha1;
    const int4* h1p = (const int4*)g_h1h;   // row = 16 int4

    int beg = g_rowptr[n], end = g_rowptr[n + 1];
    float a0 = 0.f, a1 = 0.f, a2 = 0.f, a3 = 0.f;
    float a4 = 0.f, a5 = 0.f, a6 = 0.f, a7 = 0.f;

#define AGG1_ACC(P, W)                                                          \
    {                                                                           \
        float2 f;                                                               \
        f = __half22float2(*(__half2*)&(P).x); a0 += (W) * f.x; a1 += (W) * f.y;\
        f = __half22float2(*(__half2*)&(P).y); a2 += (W) * f.x; a3 += (W) * f.y;\
        f = __half22float2(*(__half2*)&(P).z); a4 += (W) * f.x; a5 += (W) * f.y;\
        f = __half22float2(*(__half2*)&(P).w); a6 += (W) * f.x; a7 += (W) * f.y;\
    }

    int i = beg;
    for (; i + 4 <= end; i += 4) {
        int ii0 = i + half;
        int ii1 = i + 2 + half;
        int s0 = g_csrc[ii0];
        int s1 = g_csrc[ii1];
        float w0 = af[(size_t)ii0 * 4 + h];
        float w1 = af[(size_t)ii1 * 4 + h];
        int4 p0 = h1p[(size_t)s0 * 16 + c];
        int4 p1 = h1p[(size_t)s1 * 16 + c];
        AGG1_ACC(p0, w0)
        AGG1_ACC(p1, w1)
    }
    for (; i < end; i += 2) {
        int ii = i + half;
        if (ii < end) {
            int s = g_csrc[ii];
            float w0 = af[(size_t)ii * 4 + h];
            int4 p = h1p[(size_t)s * 16 + c];
            AGG1_ACC(p, w0)
        }
    }
#undef AGG1_ACC

    // combine halves: lanes c and c+16 hold partials of the same channels
    a0 += __shfl_xor_sync(0xffffffffu, a0, 16);
    a1 += __shfl_xor_sync(0xffffffffu, a1, 16);
    a2 += __shfl_xor_sync(0xffffffffu, a2, 16);
    a3 += __shfl_xor_sync(0xffffffffu, a3, 16);
    a4 += __shfl_xor_sync(0xffffffffu, a4, 16);
    a5 += __shfl_xor_sync(0xffffffffu, a5, 16);
    a6 += __shfl_xor_sync(0xffffffffu, a6, 16);
    a7 += __shfl_xor_sync(0xffffffffu, a7, 16);

    if (half == 0) {
        float r = ((const float*)g_r1)[(size_t)n * 4 + h];
        float4 bv0 = ((const float4*)b1)[2 * c];
        float4 bv1 = ((const float4*)b1)[2 * c + 1];
        float o0 = fmaxf(a0 * r + bv0.x, 0.f);
        float o1 = fmaxf(a1 * r + bv0.y, 0.f);
        float o2 = fmaxf(a2 * r + bv0.z, 0.f);
        float o3 = fmaxf(a3 * r + bv0.w, 0.f);
        float o4 = fmaxf(a4 * r + bv1.x, 0.f);
        float o5 = fmaxf(a5 * r + bv1.y, 0.f);
        float o6 = fmaxf(a6 * r + bv1.z, 0.f);
        float o7 = fmaxf(a7 * r + bv1.w, 0.f);
        int4 st;
        *(__half2*)&st.x = __floats2half2_rn(o0, o1);
        *(__half2*)&st.y = __floats2half2_rn(o2, o3);
        *(__half2*)&st.z = __floats2half2_rn(o4, o5);
        *(__half2*)&st.w = __floats2half2_rn(o6, o7);
        ((int4*)g_h1ah)[(size_t)n * 16 + c] = st;
    }
}

// ---------------- GEMM2 (tensor): h2[N,32] = h1a[N,128](f16) @ W2[128,32] + coef epilogue ----
__global__ void __launch_bounds__(128) gemm2_kernel(
    const float* __restrict__ W,
    const float* __restrict__ a_src, const float* __restrict__ a_dst, int N) {
    __shared__ __half xs[64 * 136];   // [node][k], stride 136
    __shared__ __half ws[32 * 136];   // W transposed: [n][k], stride 136

    int t = threadIdx.x;
    int lane = t & 31;
    int w = t >> 5;
    int gid = lane >> 2;
    int tig = lane & 3;
    int n0 = blockIdx.x * 64;

#pragma unroll
    for (int r = 0; r < 8; r++) {
        int f = t + r * 128;
        int node = f >> 4;
        int part = f & 15;
        int gn = n0 + node;
        int4 v = make_int4(0, 0, 0, 0);
        if (gn < N) v = ((const int4*)g_h1ah)[(size_t)gn * 16 + part];
        ((int4*)xs)[node * 17 + part] = v;
    }
#pragma unroll
    for (int r = 0; r < 32; r++) {
        int f = t + r * 128;            // k*32 + n
        int k = f >> 5;
        int n = f & 31;
        ws[n * 136 + k] = __float2half(W[f]);
    }
    __syncthreads();

    int m0 = w * 16;
    float acc[4][4];
#pragma unroll
    for (int nf = 0; nf < 4; nf++)
#pragma unroll
        for (int i = 0; i < 4; i++) acc[nf][i] = 0.f;

#pragma unroll
    for (int ks = 0; ks < 8; ks++) {
        int k0 = ks * 16 + 2 * tig;
        unsigned a0 = *(const unsigned*)&xs[(m0 + gid) * 136 + k0];
        unsigned a1 = *(const unsigned*)&xs[(m0 + gid + 8) * 136 + k0];
        unsigned a2 = *(const unsigned*)&xs[(m0 + gid) * 136 + k0 + 8];
        unsigned a3 = *(const unsigned*)&xs[(m0 + gid + 8) * 136 + k0 + 8];
#pragma unroll
        for (int nf = 0; nf < 4; nf++) {
            int nn = nf * 8 + gid;
            unsigned b0 = *(const unsigned*)&ws[nn * 136 + k0];
            unsigned b1 = *(const unsigned*)&ws[nn * 136 + k0 + 8];
            mma16816(acc[nf], a0, a1, a2, a3, b0, b1);
        }
    }

    int gn0 = n0 + m0 + gid;
    int gn1 = gn0 + 8;
    float ps0 = 0.f, ps1 = 0.f, pd0 = 0.f, pd1 = 0.f;
#pragma unroll
    for (int nf = 0; nf < 4; nf++) {
        int c = nf * 8 + 2 * tig;
        float avx = a_src[c], avy = a_src[c + 1];
        float dvx = a_dst[c], dvy = a_dst[c + 1];
        ps0 += acc[nf][0] * avx + acc[nf][1] * avy;
        ps1 += acc[nf][2] * avx + acc[nf][3] * avy;
        pd0 += acc[nf][0] * dvx + acc[nf][1] * dvy;
        pd1 += acc[nf][2] * dvx + acc[nf][3] * dvy;
        if (gn0 < N) g_h2h[(size_t)gn0 * 16 + (c >> 1)] = __floats2half2_rn(acc[nf][0], acc[nf][1]);
        if (gn1 < N) g_h2h[(size_t)gn1 * 16 + (c >> 1)] = __floats2half2_rn(acc[nf][2], acc[nf][3]);
    }
#pragma unroll
    for (int off = 1; off <= 2; off <<= 1) {
        ps0 += __shfl_xor_sync(0xffffffffu, ps0, off);
        ps1 += __shfl_xor_sync(0xffffffffu, ps1, off);
        pd0 += __shfl_xor_sync(0xffffffffu, pd0, off);
        pd1 += __shfl_xor_sync(0xffffffffu, pd1, off);
    }
    if (tig == 0) {
        if (gn0 < N) { g_as2[gn0] = ps0; g_ad2[gn0] = pd0; }
        if (gn1 < N) { g_as2[gn1] = ps1; g_ad2[gn1] = pd1; }
    }
}

// ---------------- layer 2: per-edge alpha + denominators ----------------
__global__ void alpha2_kernel(int N) {
    int n = (blockIdx.x * blockDim.x + threadIdx.x) >> 5;
    int lane = threadIdx.x & 31;
    if (n >= N) return;
    float ad = g_ad2[n];
    int beg = g_rowptr[n], end = g_rowptr[n + 1];
    float ds = 0.f;
    for (int i = beg + lane; i < end; i += 32) {
        float w = __expf(lrelu(g_as2[g_csrc[i]] + ad));
        g_alpha2[i] = w;
        ds += w;
    }
#pragma unroll
    for (int off = 16; off > 0; off >>= 1) ds += __shfl_xor_sync(0xffffffffu, ds, off);
    if (lane == 0) g_r2[n] = 1.f / ds;
}

// ---------------- layer 2: aggregation + bias + relu + final linear ----------------
// warp per node; quarter-warp per edge (4 edges/iter), lane owns channels {4c..4c+3}.
__global__ void agg2_kernel(const float* __restrict__ b2, const float* __restrict__ Wl,
                            const float* __restrict__ bl, float* __restrict__ out, int N) {
    int n = (blockIdx.x * blockDim.x + threadIdx.x) >> 5;
    int lane = threadIdx.x & 31;
    if (n >= N) return;
    int q = lane >> 3;
    int c = lane & 7;
    const int2* h2p = (const int2*)g_h2h;   // row = 8 int2
    int beg = g_rowptr[n], end = g_rowptr[n + 1];

    float4 acc = make_float4(0.f, 0.f, 0.f, 0.f);

#define AGG2_ACC(P, W)                                                          \
    {                                                                           \
        float2 f;                                                               \
        f = __half22float2(*(__half2*)&(P).x); acc.x += (W) * f.x; acc.y += (W) * f.y; \
        f = __half22float2(*(__half2*)&(P).y); acc.z += (W) * f.x; acc.w += (W) * f.y; \
    }

    int i = beg;
    for (; i + 8 <= end; i += 8) {
        int ii0 = i + q;
        int ii1 = i + 4 + q;
        int s0 = g_csrc[ii0];
        int s1 = g_csrc[ii1];
        float w0 = g_alpha2[ii0];
        float w1 = g_alpha2[ii1];
        int2 p0 = h2p[(size_t)s0 * 8 + c];
        int2 p1 = h2p[(size_t)s1 * 8 + c];
        AGG2_ACC(p0, w0)
        AGG2_ACC(p1, w1)
    }
    for (; i < end; i += 4) {
        int ii = i + q;
        if (ii < end) {
            int s = g_csrc[ii];
            float w = g_alpha2[ii];
            int2 p = h2p[(size_t)s * 8 + c];
            AGG2_ACC(p, w)
        }
    }
#undef AGG2_ACC

    // combine quarters: all lanes with the same c end up with the full channel sums
    acc.x += __shfl_xor_sync(0xffffffffu, acc.x, 8);
    acc.y += __shfl_xor_sync(0xffffffffu, acc.y, 8);
    acc.z += __shfl_xor_sync(0xffffffffu, acc.z, 8);
    acc.w += __shfl_xor_sync(0xffffffffu, acc.w, 8);
    acc.x += __shfl_xor_sync(0xffffffffu, acc.x, 16);
    acc.y += __shfl_xor_sync(0xffffffffu, acc.y, 16);
    acc.z += __shfl_xor_sync(0xffffffffu, acc.z, 16);
    acc.w += __shfl_xor_sync(0xffffffffu, acc.w, 16);

    float r = g_r2[n];
    float4 bv = ((const float4*)b2)[c];
    float4 wl = ((const float4*)Wl)[c];
    float v = fmaxf(acc.x * r + bv.x, 0.f) * wl.x
            + fmaxf(acc.y * r + bv.y, 0.f) * wl.y
            + fmaxf(acc.z * r + bv.z, 0.f) * wl.z
            + fmaxf(acc.w * r + bv.w, 0.f) * wl.w;
#pragma unroll
    for (int off = 1; off <= 4; off <<= 1) v += __shfl_xor_sync(0xffffffffu, v, off);
    if (lane == 0) out[n] = v + bl[0];
}

// ---------------- launch ----------------
extern "C" void kernel_launch(void* const* d_in, const int* in_sizes, int n_in,
                              void* d_out, int out_size) {
    const float* x    = (const float*)d_in[0];
    const int*   ei   = (const int*)d_in[1];
    const float* W1   = (const float*)d_in[3];
    const float* as1w = (const float*)d_in[4];
    const float* ad1w = (const float*)d_in[5];
    const float* b1   = (const float*)d_in[6];
    const float* W2   = (const float*)d_in[7];
    const float* as2w = (const float*)d_in[8];
    const float* ad2w = (const float*)d_in[9];
    const float* b2   = (const float*)d_in[10];
    const float* Wl   = (const float*)d_in[11];
    const float* bl   = (const float*)d_in[12];
    float* out = (float*)d_out;

    int N = in_sizes[0] / 64;
    int E = in_sizes[1] / 2;

    static cudaStream_t s2 = nullptr;
    static cudaEvent_t evRoot = nullptr, evGemm = nullptr;
    static int* degPtr = nullptr;
    if (s2 == nullptr) {  // one-time resource setup (first call is the uncaptured correctness run)
        cudaStreamCreateWithFlags(&s2, cudaStreamNonBlocking);
        cudaEventCreateWithFlags(&evRoot, cudaEventDisableTiming);
        cudaEventCreateWithFlags(&evGemm, cudaEventDisableTiming);
        cudaGetSymbolAddress((void**)&degPtr, g_deg);
    }

    int eb = (E + 255) / 256;
    int wb = (N + 7) / 8;  // warp-per-node, 8 warps per 256-thread block
    int sg = (N + SNODES - 1) / SNODES;

    // fork: gemm1 (independent of the graph) runs on s2, overlapped with CSR build
    cudaEventRecord(evRoot, 0);
    cudaStreamWaitEvent(s2, evRoot, 0);
    gemm1_kernel<<<(N + 63) / 64, 256, 0, s2>>>(x, W1, as1w, ad1w, N);
    cudaEventRecord(evGemm, s2);

    // CSR build on the main stream (parallel 3-phase scan, fillself fused into phase C)
    cudaMemsetAsync(degPtr, 0, (size_t)N * sizeof(int), 0);
    hist_kernel<<<eb, 256>>>(ei, E);
    scanA_kernel<<<sg, SBLK>>>(N);
    scanB_kernel<<<1, 64>>>(sg, N);
    scanC_kernel<<<sg, SBLK>>>(N);
    filledge_kernel<<<eb, 256>>>(ei, E);

    // join: alpha1 needs both gemm1 outputs and the CSR
    cudaStreamWaitEvent(0, evGemm, 0);

    // layer 1
    alpha1_kernel<<<wb, 256>>>(N);
    agg1_kernel<<<wb, 256>>>(b1, N);

    // layer 2
    gemm2_kernel<<<(N + 63) / 64, 128>>>(W2, as2w, ad2w, N);
    alpha2_kernel<<<wb, 256>>>(N);
    agg2_kernel<<<wb, 256>>>(b2, Wl, bl, out, N);
}